// round 1
// baseline (speedup 1.0000x reference)
#include <cuda_runtime.h>
#include <math.h>

// ---------------- problem constants ----------------
#define B_    2
#define C_    48
#define T_    16
#define H_    64
#define W_    64
#define N_    65536          // T*H*W per batch
#define HEADS_ 4
#define NSPLIT 64

// ---------------- scratch (static device globals; no allocs) ----------------
__device__ float g_qkv [(size_t)B_*576*N_];                 // 302 MB
__device__ float g_qkv2[(size_t)B_*576*N_];                 // 302 MB (also reused for FFN gated out)
__device__ float g_t192[(size_t)B_*192*N_];                 // 100 MB (attn_out, then pin out)
__device__ float g_ln  [(size_t)B_*C_*N_];                  // 25 MB
__device__ float g_part[(size_t)NSPLIT*B_*HEADS_*48*48];    // qk partials
__device__ float g_attn[(size_t)B_*HEADS_*48*48];
__device__ float g_inv [(size_t)B_*384];                    // 1/max(||q||,1e-12), 1/max(||k||,1e-12)

// ---------------- LayerNorm over channel dim ----------------
__global__ void ln_kernel(const float* __restrict__ x, const float* __restrict__ w,
                          const float* __restrict__ b, float* __restrict__ y) {
    int idx = blockIdx.x * blockDim.x + threadIdx.x;
    if (idx >= B_ * N_) return;
    int bi = idx / N_, n = idx - bi * N_;
    const float* xp = x + (size_t)bi * C_ * N_ + n;
    float v[C_];
    float mu = 0.f;
#pragma unroll
    for (int c = 0; c < C_; c++) { v[c] = xp[(size_t)c * N_]; mu += v[c]; }
    mu *= (1.f / C_);
    float var = 0.f;
#pragma unroll
    for (int c = 0; c < C_; c++) { float d = v[c] - mu; var += d * d; }
    var *= (1.f / C_);
    float inv = rsqrtf(var + 1e-5f);
    float* yp = y + (size_t)bi * C_ * N_ + n;
#pragma unroll
    for (int c = 0; c < C_; c++) yp[(size_t)c * N_] = (v[c] - mu) * inv * w[c] + b[c];
}

// ---------------- 1x1x1 conv (pointwise GEMM) ----------------
// grid: (N_/256, cout/CO_TILE, B_), block 256. Optional fused residual add.
template<int CIN, int CO_TILE>
__global__ void conv1x1_kernel(const float* __restrict__ in, const float* __restrict__ wgt,
                               const float* __restrict__ bias, const float* __restrict__ res,
                               float* __restrict__ out, int cout) {
    __shared__ float ws[CO_TILE * CIN];
    __shared__ float bs[CO_TILE];
    int tid = threadIdx.x;
    int cb = blockIdx.y * CO_TILE;
    int b  = blockIdx.z;
    for (int i = tid; i < CO_TILE * CIN; i += blockDim.x)
        ws[i] = wgt[(size_t)(cb + i / CIN) * CIN + (i % CIN)];
    for (int i = tid; i < CO_TILE; i += blockDim.x) bs[i] = bias[cb + i];
    __syncthreads();
    int n = blockIdx.x * blockDim.x + tid;
    float acc[CO_TILE];
#pragma unroll
    for (int o = 0; o < CO_TILE; o++) acc[o] = bs[o];
    const float* ip = in + (size_t)b * CIN * N_ + n;
#pragma unroll 4
    for (int c = 0; c < CIN; c++) {
        float xv = ip[(size_t)c * N_];
#pragma unroll
        for (int o = 0; o < CO_TILE; o++) acc[o] = fmaf(ws[o * CIN + c], xv, acc[o]);
    }
    float* op = out + ((size_t)b * cout + cb) * N_ + n;
    if (res) {
        const float* rp = res + ((size_t)b * cout + cb) * N_ + n;
#pragma unroll
        for (int o = 0; o < CO_TILE; o++) op[(size_t)o * N_] = acc[o] + rp[(size_t)o * N_];
    } else {
#pragma unroll
        for (int o = 0; o < CO_TILE; o++) op[(size_t)o * N_] = acc[o];
    }
}

// ---------------- grouped 3x3x3 conv, pad=1 ----------------
// Each thread computes a 1(t) x 4(h) x 4(w) output tile for one output channel.
// CIPG input channels per group, COPG output channels per group.
template<int CHTOT, int CIPG, int COPG>
__global__ void gdw_kernel(const float* __restrict__ in, const float* __restrict__ wgt,
                           const float* __restrict__ bias, float* __restrict__ out) {
    long idx = (long)blockIdx.x * blockDim.x + threadIdx.x;
    const long total = (long)B_ * CHTOT * T_ * 16 * 16;
    if (idx >= total) return;
    int wq = (int)(idx & 15);
    long rest = idx >> 4;
    int hq = (int)(rest & 15); rest >>= 4;
    int t  = (int)(rest & 15); rest >>= 4;
    int o  = (int)(rest % CHTOT);
    int b  = (int)(rest / CHTOT);
    int w0 = wq * 4, h0 = hq * 4;
    int cbase = (o / COPG) * CIPG;

    float bv = bias[o];
    float acc[4][4];
#pragma unroll
    for (int i = 0; i < 4; i++)
#pragma unroll
        for (int j = 0; j < 4; j++) acc[i][j] = bv;

    const float* wb = wgt + (size_t)o * CIPG * 27;
#pragma unroll
    for (int ci = 0; ci < CIPG; ci++) {
        float wk[27];
#pragma unroll
        for (int k = 0; k < 27; k++) wk[k] = wb[ci * 27 + k];
        const float* ip = in + (size_t)(b * CHTOT + cbase + ci) * T_ * H_ * W_;
#pragma unroll
        for (int kd = 0; kd < 3; kd++) {
            int tt = t + kd - 1;
            if ((unsigned)tt < (unsigned)T_) {
                const float* pl = ip + (size_t)tt * H_ * W_;
#pragma unroll
                for (int r = 0; r < 6; r++) {
                    int hh = h0 - 1 + r;
                    if ((unsigned)hh < (unsigned)H_) {
                        const float* rowp = pl + hh * W_;
                        float v[6];
#pragma unroll
                        for (int j = 0; j < 6; j++) {
                            int ww = w0 - 1 + j;
                            v[j] = ((unsigned)ww < (unsigned)W_) ? rowp[ww] : 0.f;
                        }
#pragma unroll
                        for (int kh = 0; kh < 3; kh++) {
                            int oh = r - kh;
                            if (oh >= 0 && oh < 4) {
                                float k0 = wk[kd * 9 + kh * 3 + 0];
                                float k1 = wk[kd * 9 + kh * 3 + 1];
                                float k2 = wk[kd * 9 + kh * 3 + 2];
#pragma unroll
                                for (int ow = 0; ow < 4; ow++)
                                    acc[oh][ow] = fmaf(k0, v[ow],
                                                   fmaf(k1, v[ow + 1],
                                                    fmaf(k2, v[ow + 2], acc[oh][ow])));
                            }
                        }
                    }
                }
            }
        }
    }
    float* op = out + ((size_t)(b * CHTOT + o) * T_ + t) * H_ * W_;
#pragma unroll
    for (int i = 0; i < 4; i++)
#pragma unroll
        for (int j = 0; j < 4; j++) op[(h0 + i) * W_ + w0 + j] = acc[i][j];
}

// ---------------- per-row L2 norm (q and k rows) ----------------
__global__ void rownorm_kernel(const float* __restrict__ qkv2, float* __restrict__ inv) {
    int row = blockIdx.x;              // 0 .. B_*384-1 (channels 0..383 per batch)
    int b = row / 384, ch = row % 384;
    const float* p = qkv2 + (size_t)(b * 576 + ch) * N_;
    float s = 0.f;
    for (int n = threadIdx.x; n < N_; n += blockDim.x) { float v = p[n]; s += v * v; }
    __shared__ float red[256];
    red[threadIdx.x] = s;
    __syncthreads();
    for (int off = 128; off; off >>= 1) {
        if (threadIdx.x < off) red[threadIdx.x] += red[threadIdx.x + off];
        __syncthreads();
    }
    if (threadIdx.x == 0) inv[row] = 1.f / fmaxf(sqrtf(red[0]), 1e-12f);
}

// ---------------- q·k^T partials: 48x48 GEMM over a 1024-slice of N ----------------
__global__ void qk_kernel(const float* __restrict__ qkv2, float* __restrict__ part) {
    int ns = blockIdx.x, h = blockIdx.y, b = blockIdx.z;
    __shared__ float qs[48][65];
    __shared__ float ks[48][65];
    int tid = threadIdx.x;
    int tx = tid & 15, ty = tid >> 4;      // 16 x 16 threads, 3x3 micro-tile each
    int c0 = tx * 3, d0 = ty * 3;
    float acc[3][3] = {};
    int nbase = ns * (N_ / NSPLIT);        // 1024 per split
    const float* qbase = qkv2 + (size_t)(b * 576 + h * 48) * N_;
    const float* kbase = qkv2 + (size_t)(b * 576 + 192 + h * 48) * N_;
    for (int off = 0; off < N_ / NSPLIT; off += 64) {
        for (int i = tid; i < 48 * 64; i += 256) {
            int c = i >> 6, nn = i & 63;
            qs[c][nn] = qbase[(size_t)c * N_ + nbase + off + nn];
            ks[c][nn] = kbase[(size_t)c * N_ + nbase + off + nn];
        }
        __syncthreads();
#pragma unroll 8
        for (int nn = 0; nn < 64; nn++) {
            float q0 = qs[c0][nn], q1 = qs[c0 + 1][nn], q2 = qs[c0 + 2][nn];
            float k0 = ks[d0][nn], k1 = ks[d0 + 1][nn], k2 = ks[d0 + 2][nn];
            acc[0][0] = fmaf(q0, k0, acc[0][0]);
            acc[0][1] = fmaf(q0, k1, acc[0][1]);
            acc[0][2] = fmaf(q0, k2, acc[0][2]);
            acc[1][0] = fmaf(q1, k0, acc[1][0]);
            acc[1][1] = fmaf(q1, k1, acc[1][1]);
            acc[1][2] = fmaf(q1, k2, acc[1][2]);
            acc[2][0] = fmaf(q2, k0, acc[2][0]);
            acc[2][1] = fmaf(q2, k1, acc[2][1]);
            acc[2][2] = fmaf(q2, k2, acc[2][2]);
        }
        __syncthreads();
    }
    float* pp = part + (((size_t)ns * B_ + b) * HEADS_ + h) * 2304;
#pragma unroll
    for (int i = 0; i < 3; i++)
#pragma unroll
        for (int j = 0; j < 3; j++) pp[(c0 + i) * 48 + d0 + j] = acc[i][j];
}

// ---------------- reduce partials, scale by inv norms & temperature, softmax ----------------
__global__ void softmax_kernel(const float* __restrict__ part, const float* __restrict__ inv,
                               const float* __restrict__ temp, float* __restrict__ attn) {
    int c = blockIdx.x, h = blockIdx.y, b = blockIdx.z;
    int d = threadIdx.x;                    // block 64, 48 active
    __shared__ float sv[48];
    __shared__ float m_s, sum_s;
    float s = 0.f;
    if (d < 48) {
        const float* pp = part + ((size_t)b * HEADS_ + h) * 2304 + c * 48 + d;
        const size_t stride = (size_t)B_ * HEADS_ * 2304;
        for (int p = 0; p < NSPLIT; p++) s += pp[(size_t)p * stride];
        s *= inv[b * 384 + h * 48 + c] * inv[b * 384 + 192 + h * 48 + d] * temp[h];
        sv[d] = s;
    }
    __syncthreads();
    if (threadIdx.x == 0) {
        float m = sv[0];
        for (int i = 1; i < 48; i++) m = fmaxf(m, sv[i]);
        m_s = m;
    }
    __syncthreads();
    float e = 0.f;
    if (d < 48) { e = expf(s - m_s); sv[d] = e; }
    __syncthreads();
    if (threadIdx.x == 0) {
        float t2 = 0.f;
        for (int i = 0; i < 48; i++) t2 += sv[i];
        sum_s = t2;
    }
    __syncthreads();
    if (d < 48) attn[(((size_t)b * HEADS_ + h) * 48 + c) * 48 + d] = e / sum_s;
}

// ---------------- out = attn @ v ----------------
__global__ void av_kernel(const float* __restrict__ qkv2, const float* __restrict__ attn,
                          float* __restrict__ out) {
    int h = blockIdx.y, b = blockIdx.z;
    __shared__ float a[48][49];
    int tid = threadIdx.x;
    for (int i = tid; i < 2304; i += 256)
        a[i / 48][i % 48] = attn[((size_t)b * HEADS_ + h) * 2304 + i];
    __syncthreads();
    int n = blockIdx.x * 256 + tid;
    const float* vb = qkv2 + (size_t)(b * 576 + 384 + h * 48) * N_ + n;
    float acc[48] = {};
#pragma unroll 4
    for (int d = 0; d < 48; d++) {
        float v = vb[(size_t)d * N_];
#pragma unroll
        for (int c = 0; c < 48; c++) acc[c] = fmaf(a[c][d], v, acc[c]);
    }
    float* op = out + (size_t)(b * 192 + h * 48) * N_ + n;
#pragma unroll
    for (int c = 0; c < 48; c++) op[(size_t)c * N_] = acc[c];
}

// ---------------- GELU(z1) * z2 gate ----------------
__global__ void gate_kernel(const float* __restrict__ z, float* __restrict__ g) {
    int idx = blockIdx.x * blockDim.x + threadIdx.x;
    if (idx >= B_ * 96 * N_) return;
    int n = idx % N_;
    int rest = idx / N_;
    int c = rest % 96;
    int b = rest / 96;
    float a  = z[(size_t)(b * 192 + c) * N_ + n];
    float b2 = z[(size_t)(b * 192 + 96 + c) * N_ + n];
    float ge = 0.5f * a * (1.f + erff(a * 0.70710678118654752f));
    g[(size_t)(b * 96 + c) * N_ + n] = ge * b2;
}

// ---------------- launcher ----------------
extern "C" void kernel_launch(void* const* d_in, const int* in_sizes, int n_in,
                              void* d_out, int out_size) {
    (void)in_sizes; (void)n_in; (void)out_size;
    const float* x      = (const float*)d_in[0];
    const float* ln1_w  = (const float*)d_in[1];
    const float* ln1_b  = (const float*)d_in[2];
    const float* qkv_w  = (const float*)d_in[3];
    const float* qkv_b  = (const float*)d_in[4];
    const float* qkvdw_w= (const float*)d_in[5];
    const float* qkvdw_b= (const float*)d_in[6];
    const float* temper = (const float*)d_in[7];
    const float* proj_w = (const float*)d_in[8];
    const float* proj_b = (const float*)d_in[9];
    const float* ln2_w  = (const float*)d_in[10];
    const float* ln2_b  = (const float*)d_in[11];
    const float* pin_w  = (const float*)d_in[12];
    const float* pin_b  = (const float*)d_in[13];
    const float* dw_w   = (const float*)d_in[14];
    const float* dw_b   = (const float*)d_in[15];
    const float* pout_w = (const float*)d_in[16];
    const float* pout_b = (const float*)d_in[17];
    float* out = (float*)d_out;

    float *qkv, *qkv2, *t192, *ln, *part, *attn, *inv;
    cudaGetSymbolAddress((void**)&qkv,  g_qkv);
    cudaGetSymbolAddress((void**)&qkv2, g_qkv2);
    cudaGetSymbolAddress((void**)&t192, g_t192);
    cudaGetSymbolAddress((void**)&ln,   g_ln);
    cudaGetSymbolAddress((void**)&part, g_part);
    cudaGetSymbolAddress((void**)&attn, g_attn);
    cudaGetSymbolAddress((void**)&inv,  g_inv);

    // ---- attention branch ----
    ln_kernel<<<(B_ * N_) / 256, 256>>>(x, ln1_w, ln1_b, ln);

    conv1x1_kernel<48, 32><<<dim3(N_ / 256, 576 / 32, B_), 256>>>(ln, qkv_w, qkv_b, nullptr, qkv, 576);

    gdw_kernel<576, 4, 4><<<(B_ * 576 * T_ * 16 * 16) / 128, 128>>>(qkv, qkvdw_w, qkvdw_b, qkv2);

    rownorm_kernel<<<B_ * 384, 256>>>(qkv2, inv);

    qk_kernel<<<dim3(NSPLIT, HEADS_, B_), 256>>>(qkv2, part);

    softmax_kernel<<<dim3(48, HEADS_, B_), 64>>>(part, inv, temper, attn);

    av_kernel<<<dim3(N_ / 256, HEADS_, B_), 256>>>(qkv2, attn, t192);

    // proj + residual(x) -> d_out
    conv1x1_kernel<192, 48><<<dim3(N_ / 256, 1, B_), 256>>>(t192, proj_w, proj_b, x, out, 48);

    // ---- FFN branch ----
    ln_kernel<<<(B_ * N_) / 256, 256>>>(out, ln2_w, ln2_b, ln);

    conv1x1_kernel<48, 32><<<dim3(N_ / 256, 192 / 32, B_), 256>>>(ln, pin_w, pin_b, nullptr, t192, 192);

    gdw_kernel<192, 1, 1><<<(B_ * 192 * T_ * 16 * 16) / 128, 128>>>(t192, dw_w, dw_b, qkv);

    gate_kernel<<<(B_ * 96 * N_) / 256, 256>>>(qkv, qkv2);

    // pout + residual(d_out) -> d_out
    conv1x1_kernel<96, 48><<<dim3(N_ / 256, 1, B_), 256>>>(qkv2, pout_w, pout_b, out, out, 48);
}